// round 3
// baseline (speedup 1.0000x reference)
#include <cuda_runtime.h>

#define DEVINL __device__ __forceinline__

namespace {

constexpr int NOFF = 44;
constexpr int H    = 16;
constexpr int N    = 8192;
constexpr int HD   = 64;
constexpr int POS_PER_CTA = 64;
constexpr int NTHREADS    = 256;
constexpr float SC = 0.125f;   // 1/sqrt(64)
constexpr int MAX_OFF = 1536;
constexpr int CHUNK = 11;      // 44 = 4 * 11

__host__ __device__ constexpr int off_at(int i) {
    return i <= 32 ? i
         : i == 33 ? 48   : i == 34 ? 64   : i == 35 ? 96
         : i == 36 ? 128  : i == 37 ? 192  : i == 38 ? 256
         : i == 39 ? 384  : i == 40 ? 512  : i == 41 ? 768
         : i == 42 ? 1024 : 1536;
}

struct Smem {
    float  se[NOFF * HD];   // 11264 B
    float  bias[NOFF];
    float2 cs[NOFF];
};

// 16-lane all-reduce sum (butterfly; masks < 16 keep traffic inside the group).
DEVINL float group16_sum(float x) {
    x += __shfl_xor_sync(0xffffffffu, x, 1);
    x += __shfl_xor_sync(0xffffffffu, x, 2);
    x += __shfl_xor_sync(0xffffffffu, x, 4);
    x += __shfl_xor_sync(0xffffffffu, x, 8);
    return x;
}

template <bool CHECK>
DEVINL void run_pos(int n, int c,
                    const float* __restrict__ qb,
                    const float* __restrict__ kb,
                    const float* __restrict__ vb,
                    float* __restrict__ ob,
                    const Smem& sm)
{
    const float4 q4 = *reinterpret_cast<const float4*>(qb + (size_t)n * HD + 4 * c);

    float s[NOFF];

    // ---- score phase, chunked to bound register pressure ----
#pragma unroll
    for (int ch = 0; ch < NOFF / CHUNK; ++ch) {
        float4 k4[CHUNK];
#pragma unroll
        for (int j = 0; j < CHUNK; ++j) {
            const int i = ch * CHUNK + j;
            const int d = off_at(i);
            if (!CHECK || (n >= d))
                k4[j] = *reinterpret_cast<const float4*>(kb + (size_t)(n - d) * HD + 4 * c);
            else
                k4[j] = make_float4(0.f, 0.f, 0.f, 0.f);
        }
#pragma unroll
        for (int j = 0; j < CHUNK; ++j) {
            const int i = ch * CHUNK + j;
            const int d = off_at(i);
            const float4 se4 = *reinterpret_cast<const float4*>(&sm.se[i * HD + 4 * c]);
            float hsum = q4.x * (k4[j].x + se4.x)
                       + q4.y * (k4[j].y + se4.y)
                       + q4.z * (k4[j].z + se4.z)
                       + q4.w * (k4[j].w + se4.w);
            hsum = group16_sum(hsum);
            const bool valid = !CHECK || (n >= d);
            s[i] = valid ? fmaf(hsum, SC, sm.bias[i]) : -1e30f;
        }
    }

    // ---- softmax (4-way trees, deferred normalization) ----
    float m0 = s[0], m1 = s[1], m2 = s[2], m3 = s[3];
#pragma unroll
    for (int i = 4; i < NOFF; i += 4) {
        m0 = fmaxf(m0, s[i]);
        m1 = fmaxf(m1, s[i + 1]);
        m2 = fmaxf(m2, s[i + 2]);
        m3 = fmaxf(m3, s[i + 3]);
    }
    const float m = fmaxf(fmaxf(m0, m1), fmaxf(m2, m3));

    float a0 = 0.f, a1 = 0.f, a2 = 0.f, a3 = 0.f;
#pragma unroll
    for (int i = 0; i < NOFF; i += 4) {
        float e0 = __expf(s[i]     - m);
        float e1 = __expf(s[i + 1] - m);
        float e2 = __expf(s[i + 2] - m);
        float e3 = __expf(s[i + 3] - m);
        s[i] = e0; s[i + 1] = e1; s[i + 2] = e2; s[i + 3] = e3;
        a0 += e0; a1 += e1; a2 += e2; a3 += e3;
    }
    const float inv = __fdividef(1.f, (a0 + a1) + (a2 + a3));

    // ---- output phase, chunked ----
    float4 o = make_float4(0.f, 0.f, 0.f, 0.f);
#pragma unroll
    for (int ch = 0; ch < NOFF / CHUNK; ++ch) {
        float4 v4[CHUNK];
#pragma unroll
        for (int j = 0; j < CHUNK; ++j) {
            const int i = ch * CHUNK + j;
            const int d = off_at(i);
            if (!CHECK || (n >= d))
                v4[j] = *reinterpret_cast<const float4*>(vb + (size_t)(n - d) * HD + 4 * c);
            else
                v4[j] = make_float4(0.f, 0.f, 0.f, 0.f);
        }
#pragma unroll
        for (int j = 0; j < CHUNK; ++j) {
            const int i = ch * CHUNK + j;
            const float2 cs = sm.cs[i];
            const float a = s[i] * cs.x;
            const float b = s[i] * cs.y;
            o.x = fmaf(a, v4[j].x, o.x);  o.x = fmaf(-b, v4[j].y, o.x);
            o.y = fmaf(b, v4[j].x, o.y);  o.y = fmaf( a, v4[j].y, o.y);
            o.z = fmaf(a, v4[j].z, o.z);  o.z = fmaf(-b, v4[j].w, o.z);
            o.w = fmaf(b, v4[j].z, o.w);  o.w = fmaf( a, v4[j].w, o.w);
        }
    }
    o.x *= inv; o.y *= inv; o.z *= inv; o.w *= inv;

    *reinterpret_cast<float4*>(ob + (size_t)n * HD + 4 * c) = o;
}

__global__ void __launch_bounds__(NTHREADS, 2)
dsqg_kernel(const float* __restrict__ q, const float* __restrict__ k,
            const float* __restrict__ v, const float* __restrict__ pos_bias,
            const float* __restrict__ se, const float* __restrict__ phase,
            float* __restrict__ out)
{
    __shared__ Smem sm;
    const int bh  = blockIdx.y;
    const int h   = bh & (H - 1);
    const int tid = threadIdx.x;

    for (int idx = tid; idx < NOFF * HD; idx += NTHREADS) sm.se[idx] = se[idx];
    if (tid < NOFF) {
        sm.bias[tid] = pos_bias[tid * H + h];
        float ss, cc;
        sincosf(phase[tid * H + h], &ss, &cc);
        sm.cs[tid] = make_float2(cc, ss);
    }
    __syncthreads();

    const size_t base = (size_t)bh * N * HD;
    const float* qb = q + base;
    const float* kb = k + base;
    const float* vb = v + base;
    float*       ob = out + base;

    const int warp = tid >> 5;
    const int lane = tid & 31;
    const int sub  = lane >> 4;            // which of the warp's 2 positions
    const int c    = lane & 15;            // dim chunk
    const int n0   = blockIdx.x * POS_PER_CTA;

    if (n0 >= MAX_OFF) {
#pragma unroll 1
        for (int it = 0; it < POS_PER_CTA / 16; ++it) {
            const int n = n0 + it * 16 + warp * 2 + sub;
            run_pos<false>(n, c, qb, kb, vb, ob, sm);
        }
    } else {
#pragma unroll 1
        for (int it = 0; it < POS_PER_CTA / 16; ++it) {
            const int n = n0 + it * 16 + warp * 2 + sub;
            run_pos<true>(n, c, qb, kb, vb, ob, sm);
        }
    }
}

} // namespace

extern "C" void kernel_launch(void* const* d_in, const int* in_sizes, int n_in,
                              void* d_out, int out_size)
{
    const float* q  = (const float*)d_in[0];
    const float* k  = (const float*)d_in[1];
    const float* v  = (const float*)d_in[2];
    const float* pb = (const float*)d_in[3];
    const float* se = (const float*)d_in[4];
    const float* ph = (const float*)d_in[5];
    float* out = (float*)d_out;

    const int B = in_sizes[0] / (H * N * HD);   // expect 2
    dim3 grid(N / POS_PER_CTA, B * H);
    dsqg_kernel<<<grid, NTHREADS>>>(q, k, v, pb, se, ph, out);
}

// round 5
// speedup vs baseline: 1.9739x; 1.9739x over previous
#include <cuda_runtime.h>

#define DEVINL __device__ __forceinline__

namespace {

constexpr int NOFF = 44;
constexpr int H    = 16;
constexpr int N    = 8192;
constexpr int HD   = 64;
constexpr int POS_PER_CTA = 128;
constexpr int NTHREADS    = 512;   // 16 warps, 1 CTA/SM
constexpr float SC = 0.125f;
constexpr int MAX_OFF = 1536;

__host__ __device__ constexpr int off_at(int i) {
    return i <= 32 ? i
         : i == 33 ? 48   : i == 34 ? 64   : i == 35 ? 96
         : i == 36 ? 128  : i == 37 ? 192  : i == 38 ? 256
         : i == 39 ? 384  : i == 40 ? 512  : i == 41 ? 768
         : i == 42 ? 1024 : 1536;
}

struct Smem {
    float  se[NOFF * HD];   // 11264 B
    float  bias[NOFF];
    float2 cs[NOFF];
};

// 8-lane all-reduce sum (butterfly inside each octet).
DEVINL float group8_sum(float x) {
    x += __shfl_xor_sync(0xffffffffu, x, 1);
    x += __shfl_xor_sync(0xffffffffu, x, 2);
    x += __shfl_xor_sync(0xffffffffu, x, 4);
    return x;
}

DEVINL float4 f4zero() { return make_float4(0.f, 0.f, 0.f, 0.f); }

// Load the two 16B chunks this thread owns from a 256B row.
// `stream` is compile-time-constant after unrolling (off_at(literal) >= 192),
// so the branch folds; evict-first for sparse single-use rows.
DEVINL void load_row2(bool stream, const float* __restrict__ row, int c,
                      float4& a, float4& b) {
    const float4* pa = reinterpret_cast<const float4*>(row + 4 * c);
    const float4* pb = reinterpret_cast<const float4*>(row + 32 + 4 * c);
    if (stream) { a = __ldcs(pa); b = __ldcs(pb); }
    else        { a = __ldg(pa);  b = __ldg(pb);  }
}

// One 8-lane group handles position n; lane c covers dims [4c,4c+4) and [32+4c,32+4c+4).
template <bool CHECK>
DEVINL void run_pos(int n, int c,
                    const float* __restrict__ qb,
                    const float* __restrict__ kb,
                    const float* __restrict__ vb,
                    float* __restrict__ ob,
                    const Smem& sm)
{
    const float* qr = qb + (size_t)n * HD;
    const float4 qa = __ldg(reinterpret_cast<const float4*>(qr + 4 * c));
    const float4 qv = __ldg(reinterpret_cast<const float4*>(qr + 32 + 4 * c));

    float s[NOFF];

    // ---- score phase: s_i = sc * (q . (k[n-d] + se_i)) + bias_i ----
#pragma unroll
    for (int ch = 0; ch < NOFF / 4; ++ch) {
        float4 ka[4], kc[4];
#pragma unroll
        for (int j = 0; j < 4; ++j) {
            const int i = ch * 4 + j;
            const int d = off_at(i);
            const bool valid = !CHECK || (n >= d);
            if (valid) load_row2(d >= 192, kb + (size_t)(n - d) * HD, c, ka[j], kc[j]);
            else { ka[j] = f4zero(); kc[j] = f4zero(); }
        }
#pragma unroll
        for (int j = 0; j < 4; ++j) {
            const int i = ch * 4 + j;
            const int d = off_at(i);
            const float4 sa = *reinterpret_cast<const float4*>(&sm.se[i * HD + 4 * c]);
            const float4 sb = *reinterpret_cast<const float4*>(&sm.se[i * HD + 32 + 4 * c]);
            float p = qa.x * (ka[j].x + sa.x);
            p = fmaf(qa.y, ka[j].y + sa.y, p);
            p = fmaf(qa.z, ka[j].z + sa.z, p);
            p = fmaf(qa.w, ka[j].w + sa.w, p);
            float p2 = qv.x * (kc[j].x + sb.x);
            p2 = fmaf(qv.y, kc[j].y + sb.y, p2);
            p2 = fmaf(qv.z, kc[j].z + sb.z, p2);
            p2 = fmaf(qv.w, kc[j].w + sb.w, p2);
            float hsum = group8_sum(p + p2);
            const bool valid = !CHECK || (n >= d);
            s[i] = valid ? fmaf(hsum, SC, sm.bias[i]) : -1e30f;
        }
    }

    // ---- softmax (4-way trees, deferred normalization) ----
    float m0 = s[0], m1 = s[1], m2 = s[2], m3 = s[3];
#pragma unroll
    for (int i = 4; i < NOFF; i += 4) {
        m0 = fmaxf(m0, s[i]);
        m1 = fmaxf(m1, s[i + 1]);
        m2 = fmaxf(m2, s[i + 2]);
        m3 = fmaxf(m3, s[i + 3]);
    }
    const float m = fmaxf(fmaxf(m0, m1), fmaxf(m2, m3));

    float a0 = 0.f, a1 = 0.f, a2 = 0.f, a3 = 0.f;
#pragma unroll
    for (int i = 0; i < NOFF; i += 4) {
        float e0 = __expf(s[i]     - m);
        float e1 = __expf(s[i + 1] - m);
        float e2 = __expf(s[i + 2] - m);
        float e3 = __expf(s[i + 3] - m);
        s[i] = e0; s[i + 1] = e1; s[i + 2] = e2; s[i + 3] = e3;
        a0 += e0; a1 += e1; a2 += e2; a3 += e3;
    }
    const float inv = __fdividef(1.f, (a0 + a1) + (a2 + a3));

    // ---- output phase ----
    float4 oa = f4zero(), ob4 = f4zero();
#pragma unroll
    for (int ch = 0; ch < NOFF / 4; ++ch) {
        float4 va[4], vc[4];
#pragma unroll
        for (int j = 0; j < 4; ++j) {
            const int i = ch * 4 + j;
            const int d = off_at(i);
            const bool valid = !CHECK || (n >= d);
            if (valid) load_row2(d >= 192, vb + (size_t)(n - d) * HD, c, va[j], vc[j]);
            else { va[j] = f4zero(); vc[j] = f4zero(); }
        }
#pragma unroll
        for (int j = 0; j < 4; ++j) {
            const int i = ch * 4 + j;
            const float2 cs = sm.cs[i];
            const float a = s[i] * cs.x;
            const float b = s[i] * cs.y;
            oa.x = fmaf(a, va[j].x, oa.x);   oa.x = fmaf(-b, va[j].y, oa.x);
            oa.y = fmaf(b, va[j].x, oa.y);   oa.y = fmaf( a, va[j].y, oa.y);
            oa.z = fmaf(a, va[j].z, oa.z);   oa.z = fmaf(-b, va[j].w, oa.z);
            oa.w = fmaf(b, va[j].z, oa.w);   oa.w = fmaf( a, va[j].w, oa.w);
            ob4.x = fmaf(a, vc[j].x, ob4.x); ob4.x = fmaf(-b, vc[j].y, ob4.x);
            ob4.y = fmaf(b, vc[j].x, ob4.y); ob4.y = fmaf( a, vc[j].y, ob4.y);
            ob4.z = fmaf(a, vc[j].z, ob4.z); ob4.z = fmaf(-b, vc[j].w, ob4.z);
            ob4.w = fmaf(b, vc[j].z, ob4.w); ob4.w = fmaf( a, vc[j].w, ob4.w);
        }
    }
    oa.x *= inv; oa.y *= inv; oa.z *= inv; oa.w *= inv;
    ob4.x *= inv; ob4.y *= inv; ob4.z *= inv; ob4.w *= inv;

    float* orow = ob + (size_t)n * HD;
    *reinterpret_cast<float4*>(orow + 4 * c)      = oa;
    *reinterpret_cast<float4*>(orow + 32 + 4 * c) = ob4;
}

__global__ void __launch_bounds__(NTHREADS, 1)
dsqg_kernel(const float* __restrict__ q, const float* __restrict__ k,
            const float* __restrict__ v, const float* __restrict__ pos_bias,
            const float* __restrict__ se, const float* __restrict__ phase,
            float* __restrict__ out)
{
    __shared__ Smem sm;
    const int bh  = blockIdx.y;
    const int h   = bh & (H - 1);
    const int tid = threadIdx.x;

    for (int idx = tid; idx < NOFF * HD; idx += NTHREADS) sm.se[idx] = se[idx];
    if (tid < NOFF) {
        sm.bias[tid] = pos_bias[tid * H + h];
        float ss, cc;
        sincosf(phase[tid * H + h], &ss, &cc);
        sm.cs[tid] = make_float2(cc, ss);
    }
    __syncthreads();

    const size_t base = (size_t)bh * N * HD;
    const float* qb = q + base;
    const float* kb = k + base;
    const float* vb = v + base;
    float*       ob = out + base;

    const int warp = tid >> 5;
    const int lane = tid & 31;
    const int g    = lane >> 3;   // group in warp: 4 positions per warp
    const int c    = lane & 7;    // dim chunk within group
    const int n0   = blockIdx.x * POS_PER_CTA;

    if (n0 >= MAX_OFF) {
#pragma unroll 1
        for (int it = 0; it < POS_PER_CTA / 64; ++it) {
            const int n = n0 + it * 64 + warp * 4 + g;
            run_pos<false>(n, c, qb, kb, vb, ob, sm);
        }
    } else {
#pragma unroll 1
        for (int it = 0; it < POS_PER_CTA / 64; ++it) {
            const int n = n0 + it * 64 + warp * 4 + g;
            run_pos<true>(n, c, qb, kb, vb, ob, sm);
        }
    }
}

} // namespace

extern "C" void kernel_launch(void* const* d_in, const int* in_sizes, int n_in,
                              void* d_out, int out_size)
{
    const float* q  = (const float*)d_in[0];
    const float* k  = (const float*)d_in[1];
    const float* v  = (const float*)d_in[2];
    const float* pb = (const float*)d_in[3];
    const float* se = (const float*)d_in[4];
    const float* ph = (const float*)d_in[5];
    float* out = (float*)d_out;

    const int B = in_sizes[0] / (H * N * HD);   // expect 2
    dim3 grid(N / POS_PER_CTA, B * H);
    dsqg_kernel<<<grid, NTHREADS>>>(q, k, v, pb, se, ph, out);
}

// round 6
// speedup vs baseline: 2.3819x; 1.2067x over previous
#include <cuda_runtime.h>

#define DEVINL __device__ __forceinline__

namespace {

constexpr int NOFF = 44;
constexpr int H    = 16;
constexpr int N    = 8192;
constexpr int HD   = 64;
constexpr int POS_PER_CTA = 128;   // 16 warps * 4 groups * 2 positions
constexpr int NTHREADS    = 512;
constexpr float SC = 0.125f;
constexpr int MAX_OFF = 1536;

__host__ __device__ constexpr int off_at(int i) {
    return i <= 32 ? i
         : i == 33 ? 48   : i == 34 ? 64   : i == 35 ? 96
         : i == 36 ? 128  : i == 37 ? 192  : i == 38 ? 256
         : i == 39 ? 384  : i == 40 ? 512  : i == 41 ? 768
         : i == 42 ? 1024 : 1536;
}

struct Smem {
    float  se[NOFF * HD];
    float  bias[NOFF];
    float2 cs[NOFF];
};

DEVINL float grp_sum(float x) {
    x += __shfl_xor_sync(0xffffffffu, x, 1);
    x += __shfl_xor_sync(0xffffffffu, x, 2);
    x += __shfl_xor_sync(0xffffffffu, x, 4);
    return x;
}
DEVINL float grp_max(float x) {
    x = fmaxf(x, __shfl_xor_sync(0xffffffffu, x, 1));
    x = fmaxf(x, __shfl_xor_sync(0xffffffffu, x, 2));
    x = fmaxf(x, __shfl_xor_sync(0xffffffffu, x, 4));
    return x;
}

DEVINL float4 f4zero() { return make_float4(0.f, 0.f, 0.f, 0.f); }

// Load the two 16B chunks this thread owns from a 256B row.
DEVINL void load_row2(bool stream, const float* __restrict__ row, int c,
                      float4& a, float4& b) {
    const float4* pa = reinterpret_cast<const float4*>(row + 4 * c);
    const float4* pb = reinterpret_cast<const float4*>(row + 32 + 4 * c);
    if (stream) { a = __ldcs(pa); b = __ldcs(pb); }
    else        { a = __ldg(pa);  b = __ldg(pb);  }
}

// One 8-lane group handles the position pair (n, n+1); lane c covers dims
// [4c,4c+4) and [32+4c,32+4c+4). Scores are DISTRIBUTED: score (p,i) is kept
// only in lane (i&7), register slot (i>>3).
template <bool CHECK>
DEVINL void run_pair(int n, int c,
                     const float* __restrict__ qb,
                     const float* __restrict__ kb,
                     const float* __restrict__ vb,
                     float* __restrict__ ob,
                     const Smem& sm)
{
    const float* qr = qb + (size_t)n * HD;
    const float4 q0a = __ldg(reinterpret_cast<const float4*>(qr + 4 * c));
    const float4 q0b = __ldg(reinterpret_cast<const float4*>(qr + 32 + 4 * c));
    const float4 q1a = __ldg(reinterpret_cast<const float4*>(qr + HD + 4 * c));
    const float4 q1b = __ldg(reinterpret_cast<const float4*>(qr + HD + 32 + 4 * c));

    float sl[2][6];
#pragma unroll
    for (int p = 0; p < 2; ++p)
#pragma unroll
        for (int j = 0; j < 6; ++j) sl[p][j] = -1e30f;

    // dot for (position p, offset i) against row data (ra, rb); i, p compile-const.
    auto dot = [&](int i, int p, const float4& ra, const float4& rb, bool valid) {
        const float4 sa = *reinterpret_cast<const float4*>(&sm.se[i * HD + 4 * c]);
        const float4 sb = *reinterpret_cast<const float4*>(&sm.se[i * HD + 32 + 4 * c]);
        const float4& qa = p ? q1a : q0a;
        const float4& qv = p ? q1b : q0b;
        float t = qa.x * (ra.x + sa.x);
        t = fmaf(qa.y, ra.y + sa.y, t);
        t = fmaf(qa.z, ra.z + sa.z, t);
        t = fmaf(qa.w, ra.w + sa.w, t);
        float t2 = qv.x * (rb.x + sb.x);
        t2 = fmaf(qv.y, rb.y + sb.y, t2);
        t2 = fmaf(qv.z, rb.z + sb.z, t2);
        t2 = fmaf(qv.w, rb.w + sb.w, t2);
        const float hs = grp_sum(t + t2);
        const float s = valid ? fmaf(hs, SC, sm.bias[i]) : -1e30f;
        if ((i & 7) == c) sl[p][i >> 3] = s;
    };

    // ---- score phase ----
    // single rows: row n+1 -> (p1, i=0); row n-32 -> (p0, i=32)
    {
        float4 a0, b0, a1, b1;
        load_row2(false, kb + (size_t)(n + 1) * HD, c, a0, b0);
        const bool v32 = !CHECK || (n >= 32);
        if (v32) load_row2(false, kb + (size_t)(n - 32) * HD, c, a1, b1);
        else { a1 = f4zero(); b1 = f4zero(); }
        dot(0, 1, a0, b0, true);
        dot(32, 0, a1, b1, v32);
    }
    // shared rows: row n-i serves (p0,i) and (p1,i+1), i = 0..31
#pragma unroll
    for (int ch = 0; ch < 8; ++ch) {
        float4 ka[4], kc[4];
#pragma unroll
        for (int j = 0; j < 4; ++j) {
            const int i = ch * 4 + j;
            const bool valid = !CHECK || (n >= i);
            if (valid) load_row2(false, kb + (size_t)(n - i) * HD, c, ka[j], kc[j]);
            else { ka[j] = f4zero(); kc[j] = f4zero(); }
        }
#pragma unroll
        for (int j = 0; j < 4; ++j) {
            const int i = ch * 4 + j;
            const bool valid = !CHECK || (n >= i);
            dot(i,     0, ka[j], kc[j], valid);
            dot(i + 1, 1, ka[j], kc[j], valid);   // n+1 >= i+1 <=> n >= i
        }
    }
    // sparse offsets (idx 33..43): 2 rows each (one per position)
#pragma unroll
    for (int ii = 33; ii < 44; ii += 2) {
        constexpr int MAXT = 2;
        float4 ra[4], rb[4];
#pragma unroll
        for (int t = 0; t < MAXT; ++t) {
            if (ii + t < 44) {
                const int i = ii + t;
                const int d = off_at(i);
                const bool st = d >= 192;
                const bool v0 = !CHECK || (n >= d);
                const bool v1 = !CHECK || (n + 1 >= d);
                if (v0) load_row2(st, kb + (size_t)(n - d) * HD, c, ra[2 * t], rb[2 * t]);
                else { ra[2 * t] = f4zero(); rb[2 * t] = f4zero(); }
                if (v1) load_row2(st, kb + (size_t)(n + 1 - d) * HD, c, ra[2 * t + 1], rb[2 * t + 1]);
                else { ra[2 * t + 1] = f4zero(); rb[2 * t + 1] = f4zero(); }
            }
        }
#pragma unroll
        for (int t = 0; t < MAXT; ++t) {
            if (ii + t < 44) {
                const int i = ii + t;
                const int d = off_at(i);
                dot(i, 0, ra[2 * t],     rb[2 * t],     !CHECK || (n >= d));
                dot(i, 1, ra[2 * t + 1], rb[2 * t + 1], !CHECK || (n + 1 >= d));
            }
        }
    }

    // ---- softmax (distributed; exp count 8x lower than replicated) ----
    float inv[2];
    float ee[2][6];
#pragma unroll
    for (int p = 0; p < 2; ++p) {
        float m = sl[p][0];
#pragma unroll
        for (int j = 1; j < 6; ++j) m = fmaxf(m, sl[p][j]);
        m = grp_max(m);
        float sum = 0.f;
#pragma unroll
        for (int j = 0; j < 6; ++j) {
            const float e = __expf(sl[p][j] - m);   // unused/invalid slots -> 0
            ee[p][j] = e;
            sum += e;
        }
        sum = grp_sum(sum);
        inv[p] = __fdividef(1.f, sum);
    }

    // weight (a,b) for (p,i): broadcast e from owner lane, fold inv + cos/sin.
    auto wgt = [&](int i, int p) -> float2 {
        const float e = __shfl_sync(0xffffffffu, ee[p][i >> 3], i & 7, 8);
        const float pw = e * inv[p];
        const float2 cs = sm.cs[i];
        return make_float2(pw * cs.x, pw * cs.y);
    };
    float4 o0a = f4zero(), o0b = f4zero(), o1a = f4zero(), o1b = f4zero();
    auto acc = [&](const float2 w, const float4& va, const float4& vbv,
                   float4& oa, float4& obv) {
        oa.x = fmaf(w.x, va.x, oa.x);   oa.x = fmaf(-w.y, va.y, oa.x);
        oa.y = fmaf(w.y, va.x, oa.y);   oa.y = fmaf( w.x, va.y, oa.y);
        oa.z = fmaf(w.x, va.z, oa.z);   oa.z = fmaf(-w.y, va.w, oa.z);
        oa.w = fmaf(w.y, va.z, oa.w);   oa.w = fmaf( w.x, va.w, oa.w);
        obv.x = fmaf(w.x, vbv.x, obv.x); obv.x = fmaf(-w.y, vbv.y, obv.x);
        obv.y = fmaf(w.y, vbv.x, obv.y); obv.y = fmaf( w.x, vbv.y, obv.y);
        obv.z = fmaf(w.x, vbv.z, obv.z); obv.z = fmaf( w.x, vbv.w, obv.z);
        obv.w = fmaf(w.y, vbv.z, obv.w); obv.w = fmaf( w.x, vbv.w, obv.w);
    };
    // NOTE: fix typo risk — write acc fully explicitly below instead.

    // ---- output phase (mirrors score row structure) ----
    // (invalid contributions have e == 0, so zeroed rows are safe)
    {
        float4 a0, b0, a1, b1;
        load_row2(false, vb + (size_t)(n + 1) * HD, c, a0, b0);
        const bool v32 = !CHECK || (n >= 32);
        if (v32) load_row2(false, vb + (size_t)(n - 32) * HD, c, a1, b1);
        else { a1 = f4zero(); b1 = f4zero(); }
        {
            const float2 w = wgt(0, 1);
            o1a.x = fmaf(w.x, a0.x, o1a.x); o1a.x = fmaf(-w.y, a0.y, o1a.x);
            o1a.y = fmaf(w.y, a0.x, o1a.y); o1a.y = fmaf( w.x, a0.y, o1a.y);
            o1a.z = fmaf(w.x, a0.z, o1a.z); o1a.z = fmaf(-w.y, a0.w, o1a.z);
            o1a.w = fmaf(w.y, a0.z, o1a.w); o1a.w = fmaf( w.x, a0.w, o1a.w);
            o1b.x = fmaf(w.x, b0.x, o1b.x); o1b.x = fmaf(-w.y, b0.y, o1b.x);
            o1b.y = fmaf(w.y, b0.x, o1b.y); o1b.y = fmaf( w.x, b0.y, o1b.y);
            o1b.z = fmaf(w.x, b0.z, o1b.z); o1b.z = fmaf(-w.y, b0.w, o1b.z);
            o1b.w = fmaf(w.y, b0.z, o1b.w); o1b.w = fmaf( w.x, b0.w, o1b.w);
        }
        {
            const float2 w = wgt(32, 0);
            o0a.x = fmaf(w.x, a1.x, o0a.x); o0a.x = fmaf(-w.y, a1.y, o0a.x);
            o0a.y = fmaf(w.y, a1.x, o0a.y); o0a.y = fmaf( w.x, a1.y, o0a.y);
            o0a.z = fmaf(w.x, a1.z, o0a.z); o0a.z = fmaf(-w.y, a1.w, o0a.z);
            o0a.w = fmaf(w.y, a1.z, o0a.w); o0a.w = fmaf( w.x, a1.w, o0a.w);
            o0b.x = fmaf(w.x, b1.x, o0b.x); o0b.x = fmaf(-w.y, b1.y, o0b.x);
            o0b.y = fmaf(w.y, b1.x, o0b.y); o0b.y = fmaf( w.x, b1.y, o0b.y);
            o0b.z = fmaf(w.x, b1.z, o0b.z); o0b.z = fmaf(-w.y, b1.w, o0b.z);
            o0b.w = fmaf(w.y, b1.z, o0b.w); o0b.w = fmaf( w.x, b1.w, o0b.w);
        }
    }
#pragma unroll
    for (int ch = 0; ch < 8; ++ch) {
        float4 va[4], vc[4];
#pragma unroll
        for (int j = 0; j < 4; ++j) {
            const int i = ch * 4 + j;
            const bool valid = !CHECK || (n >= i);
            if (valid) load_row2(false, vb + (size_t)(n - i) * HD, c, va[j], vc[j]);
            else { va[j] = f4zero(); vc[j] = f4zero(); }
        }
#pragma unroll
        for (int j = 0; j < 4; ++j) {
            const int i = ch * 4 + j;
            {
                const float2 w = wgt(i, 0);
                o0a.x = fmaf(w.x, va[j].x, o0a.x); o0a.x = fmaf(-w.y, va[j].y, o0a.x);
                o0a.y = fmaf(w.y, va[j].x, o0a.y); o0a.y = fmaf( w.x, va[j].y, o0a.y);
                o0a.z = fmaf(w.x, va[j].z, o0a.z); o0a.z = fmaf(-w.y, va[j].w, o0a.z);
                o0a.w = fmaf(w.y, va[j].z, o0a.w); o0a.w = fmaf( w.x, va[j].w, o0a.w);
                o0b.x = fmaf(w.x, vc[j].x, o0b.x); o0b.x = fmaf(-w.y, vc[j].y, o0b.x);
                o0b.y = fmaf(w.y, vc[j].x, o0b.y); o0b.y = fmaf( w.x, vc[j].y, o0b.y);
                o0b.z = fmaf(w.x, vc[j].z, o0b.z); o0b.z = fmaf(-w.y, vc[j].w, o0b.z);
                o0b.w = fmaf(w.y, vc[j].z, o0b.w); o0b.w = fmaf( w.x, vc[j].w, o0b.w);
            }
            {
                const float2 w = wgt(i + 1, 1);
                o1a.x = fmaf(w.x, va[j].x, o1a.x); o1a.x = fmaf(-w.y, va[j].y, o1a.x);
                o1a.y = fmaf(w.y, va[j].x, o1a.y); o1a.y = fmaf( w.x, va[j].y, o1a.y);
                o1a.z = fmaf(w.x, va[j].z, o1a.z); o1a.z = fmaf(-w.y, va[j].w, o1a.z);
                o1a.w = fmaf(w.y, va[j].z, o1a.w); o1a.w = fmaf( w.x, va[j].w, o1a.w);
                o1b.x = fmaf(w.x, vc[j].x, o1b.x); o1b.x = fmaf(-w.y, vc[j].y, o1b.x);
                o1b.y = fmaf(w.y, vc[j].x, o1b.y); o1b.y = fmaf( w.x, vc[j].y, o1b.y);
                o1b.z = fmaf(w.x, vc[j].z, o1b.z); o1b.z = fmaf(-w.y, vc[j].w, o1b.z);
                o1b.w = fmaf(w.y, vc[j].z, o1b.w); o1b.w = fmaf( w.x, vc[j].w, o1b.w);
            }
        }
    }
#pragma unroll
    for (int ii = 33; ii < 44; ii += 2) {
        constexpr int MAXT = 2;
        float4 ra[4], rb[4];
#pragma unroll
        for (int t = 0; t < MAXT; ++t) {
            if (ii + t < 44) {
                const int i = ii + t;
                const int d = off_at(i);
                const bool st = d >= 192;
                const bool v0 = !CHECK || (n >= d);
                const bool v1 = !CHECK || (n + 1 >= d);
                if (v0) load_row2(st, vb + (size_t)(n - d) * HD, c, ra[2 * t], rb[2 * t]);
                else { ra[2 * t] = f4zero(); rb[2 * t] = f4zero(); }
                if (v1) load_row2(st, vb + (size_t)(n + 1 - d) * HD, c, ra[2 * t + 1], rb[2 * t + 1]);
                else { ra[2 * t + 1] = f4zero(); rb[2 * t + 1] = f4zero(); }
            }
        }
#pragma unroll
        for (int t = 0; t < MAXT; ++t) {
            if (ii + t < 44) {
                const int i = ii + t;
                {
                    const float2 w = wgt(i, 0);
                    const float4& va = ra[2 * t];
                    const float4& vc = rb[2 * t];
                    o0a.x = fmaf(w.x, va.x, o0a.x); o0a.x = fmaf(-w.y, va.y, o0a.x);
                    o0a.y = fmaf(w.y, va.x, o0a.y); o0a.y = fmaf( w.x, va.y, o0a.y);
                    o0a.z = fmaf(w.x, va.z, o0a.z); o0a.z = fmaf(-w.y, va.w, o0a.z);
                    o0a.w = fmaf(w.y, va.z, o0a.w); o0a.w = fmaf( w.x, va.w, o0a.w);
                    o0b.x = fmaf(w.x, vc.x, o0b.x); o0b.x = fmaf(-w.y, vc.y, o0b.x);
                    o0b.y = fmaf(w.y, vc.x, o0b.y); o0b.y = fmaf( w.x, vc.y, o0b.y);
                    o0b.z = fmaf(w.x, vc.z, o0b.z); o0b.z = fmaf(-w.y, vc.w, o0b.z);
                    o0b.w = fmaf(w.y, vc.z, o0b.w); o0b.w = fmaf( w.x, vc.w, o0b.w);
                }
                {
                    const float2 w = wgt(i, 1);
                    const float4& va = ra[2 * t + 1];
                    const float4& vc = rb[2 * t + 1];
                    o1a.x = fmaf(w.x, va.x, o1a.x); o1a.x = fmaf(-w.y, va.y, o1a.x);
                    o1a.y = fmaf(w.y, va.x, o1a.y); o1a.y = fmaf( w.x, va.y, o1a.y);
                    o1a.z = fmaf(w.x, va.z, o1a.z); o1a.z = fmaf(-w.y, va.w, o1a.z);
                    o1a.w = fmaf(w.y, va.z, o1a.w); o1a.w = fmaf( w.x, va.w, o1a.w);
                    o1b.x = fmaf(w.x, vc.x, o1b.x); o1b.x = fmaf(-w.y, vc.y, o1b.x);
                    o1b.y = fmaf(w.y, vc.x, o1b.y); o1b.y = fmaf( w.x, vc.y, o1b.y);
                    o1b.z = fmaf(w.x, vc.z, o1b.z); o1b.z = fmaf(-w.y, vc.w, o1b.z);
                    o1b.w = fmaf(w.y, vc.z, o1b.w); o1b.w = fmaf( w.x, vc.w, o1b.w);
                }
            }
        }
    }

    float* orow = ob + (size_t)n * HD;
    *reinterpret_cast<float4*>(orow + 4 * c)            = o0a;
    *reinterpret_cast<float4*>(orow + 32 + 4 * c)       = o0b;
    *reinterpret_cast<float4*>(orow + HD + 4 * c)       = o1a;
    *reinterpret_cast<float4*>(orow + HD + 32 + 4 * c)  = o1b;

    (void)acc; // unused helper kept out of codegen
}

__global__ void __launch_bounds__(NTHREADS, 1)
dsqg_kernel(const float* __restrict__ q, const float* __restrict__ k,
            const float* __restrict__ v, const float* __restrict__ pos_bias,
            const float* __restrict__ se, const float* __restrict__ phase,
            float* __restrict__ out)
{
    __shared__ Smem sm;
    const int bh  = blockIdx.y;
    const int h   = bh & (H - 1);
    const int tid = threadIdx.x;

    for (int idx = tid; idx < NOFF * HD; idx += NTHREADS) sm.se[idx] = se[idx];
    if (tid < NOFF) {
        sm.bias[tid] = pos_bias[tid * H + h];
        float ss, cc;
        sincosf(phase[tid * H + h], &ss, &cc);
        sm.cs[tid] = make_float2(cc, ss);
    }
    __syncthreads();

    const size_t base = (size_t)bh * N * HD;
    const float* qb = q + base;
    const float* kb = k + base;
    const float* vb = v + base;
    float*       ob = out + base;

    const int warp = tid >> 5;
    const int lane = tid & 31;
    const int g    = lane >> 3;   // group in warp
    const int c    = lane & 7;    // dim chunk within group
    const int n0   = blockIdx.x * POS_PER_CTA;
    const int n    = n0 + (warp * 4 + g) * 2;

    if (n0 >= MAX_OFF) run_pair<false>(n, c, qb, kb, vb, ob, sm);
    else               run_pair<true >(n, c, qb, kb, vb, ob, sm);
}

} // namespace

extern "C" void kernel_launch(void* const* d_in, const int* in_sizes, int n_in,
                              void* d_out, int out_size)
{
    const float* q  = (const float*)d_in[0];
    const float* k  = (const float*)d_in[1];
    const float* v  = (const float*)d_in[2];
    const float* pb = (const float*)d_in[3];
    const float* se = (const float*)d_in[4];
    const float* ph = (const float*)d_in[5];
    float* out = (float*)d_out;

    const int B = in_sizes[0] / (H * N * HD);   // expect 2
    dim3 grid(N / POS_PER_CTA, B * H);
    dsqg_kernel<<<grid, NTHREADS>>>(q, k, v, pb, se, ph, out);
}

// round 7
// speedup vs baseline: 2.6174x; 1.0989x over previous
#include <cuda_runtime.h>

#define DEVINL __device__ __forceinline__

namespace {

constexpr int NOFF = 44;
constexpr int H    = 16;
constexpr int NPOS = 8192;
constexpr int HD   = 64;
constexpr int POS_PER_CTA = 256;   // 16 warps * 4 groups * 4 positions
constexpr int NTHREADS    = 512;
constexpr float SC = 0.125f;
constexpr int MAX_OFF = 1536;
constexpr unsigned FULL = 0xffffffffu;

__host__ __device__ constexpr int off_at(int i) {
    return i <= 32 ? i
         : i == 33 ? 48   : i == 34 ? 64   : i == 35 ? 96
         : i == 36 ? 128  : i == 37 ? 192  : i == 38 ? 256
         : i == 39 ? 384  : i == 40 ? 512  : i == 41 ? 768
         : i == 42 ? 1024 : 1536;
}

struct Smem {
    float  se[NOFF * HD];
    float  bias[NOFF];
    float2 cs[NOFF];
    int    doff[NOFF];
};

DEVINL float grp_sum(float x) {
    x += __shfl_xor_sync(FULL, x, 1);
    x += __shfl_xor_sync(FULL, x, 2);
    x += __shfl_xor_sync(FULL, x, 4);
    return x;
}
DEVINL float grp_max(float x) {
    x = fmaxf(x, __shfl_xor_sync(FULL, x, 1));
    x = fmaxf(x, __shfl_xor_sync(FULL, x, 2));
    x = fmaxf(x, __shfl_xor_sync(FULL, x, 4));
    return x;
}

DEVINL float4 f4zero() { return make_float4(0.f, 0.f, 0.f, 0.f); }

DEVINL void load_row2(bool stream, const float* __restrict__ row, int c,
                      float4& a, float4& b) {
    const float4* pa = reinterpret_cast<const float4*>(row + 4 * c);
    const float4* pb = reinterpret_cast<const float4*>(row + 32 + 4 * c);
    if (stream) { a = __ldcs(pa); b = __ldcs(pb); }
    else        { a = __ldg(pa);  b = __ldg(pb);  }
}

// per-lane 8-dim dot: q . r
DEVINL float d8(const float4& qa, const float4& qb,
                const float4& ra, const float4& rb) {
    float t = qa.x * ra.x;
    t = fmaf(qa.y, ra.y, t);
    t = fmaf(qa.z, ra.z, t);
    t = fmaf(qa.w, ra.w, t);
    t = fmaf(qb.x, rb.x, t);
    t = fmaf(qb.y, rb.y, t);
    t = fmaf(qb.z, rb.z, t);
    t = fmaf(qb.w, rb.w, t);
    return t;
}
// per-lane 8-dim dot with additive bias row: q . (r + s)
DEVINL float d8s(const float4& qa, const float4& qb,
                 const float4& ra, const float4& rb,
                 const float4& sa, const float4& sb) {
    float t = qa.x * (ra.x + sa.x);
    t = fmaf(qa.y, ra.y + sa.y, t);
    t = fmaf(qa.z, ra.z + sa.z, t);
    t = fmaf(qa.w, ra.w + sa.w, t);
    t = fmaf(qb.x, rb.x + sb.x, t);
    t = fmaf(qb.y, rb.y + sb.y, t);
    t = fmaf(qb.z, rb.z + sb.z, t);
    t = fmaf(qb.w, rb.w + sb.w, t);
    return t;
}

// 8 simultaneous 8-lane reductions in 7 shfl:
// lane c of the 8-lane group returns sum over lanes of v[c].
DEVINL float treduce8(const float (&v)[8], int c) {
    const bool h4 = (c & 4) != 0;
    float k0 = (h4 ? v[4] : v[0]) + __shfl_xor_sync(FULL, h4 ? v[0] : v[4], 4);
    float k1 = (h4 ? v[5] : v[1]) + __shfl_xor_sync(FULL, h4 ? v[1] : v[5], 4);
    float k2 = (h4 ? v[6] : v[2]) + __shfl_xor_sync(FULL, h4 ? v[2] : v[6], 4);
    float k3 = (h4 ? v[7] : v[3]) + __shfl_xor_sync(FULL, h4 ? v[3] : v[7], 4);
    const bool h2 = (c & 2) != 0;
    float m0 = (h2 ? k2 : k0) + __shfl_xor_sync(FULL, h2 ? k0 : k2, 2);
    float m1 = (h2 ? k3 : k1) + __shfl_xor_sync(FULL, h2 ? k1 : k3, 2);
    const bool h1 = (c & 1) != 0;
    return (h1 ? m1 : m0) + __shfl_xor_sync(FULL, h1 ? m0 : m1, 1);
}

// One 8-lane group handles positions n..n+3; lane c covers dims [4c,4c+4)
// and [32+4c,32+4c+4). Score (p,i) lives in lane i&7, slot i>>3.
template <bool CHECK>
DEVINL void run_quad(int n, int c,
                     const float* __restrict__ qb,
                     const float* __restrict__ kb,
                     const float* __restrict__ vb,
                     float* __restrict__ ob,
                     const Smem& sm)
{
    const float* qr = qb + (size_t)n * HD;
    float4 qA[4], qB[4];
#pragma unroll
    for (int p = 0; p < 4; ++p) {
        qA[p] = __ldg(reinterpret_cast<const float4*>(qr + p * HD + 4 * c));
        qB[p] = __ldg(reinterpret_cast<const float4*>(qr + p * HD + 32 + 4 * c));
    }

    float sl[4][6];

    // ---- dense batches b = 0..3 (offsets 8b..8b+7) ----
#pragma unroll
    for (int b = 0; b < 4; ++b) {
        float part[4][8];
        // seed with q . se  (replaces the k+se adds; same fma-pipe cost)
#pragma unroll
        for (int jj = 0; jj < 8; ++jj) {
            const int i = 8 * b + jj;
            const float4 sa = *reinterpret_cast<const float4*>(&sm.se[i * HD + 4 * c]);
            const float4 sb = *reinterpret_cast<const float4*>(&sm.se[i * HD + 32 + 4 * c]);
#pragma unroll
            for (int p = 0; p < 4; ++p)
                part[p][jj] = d8(qA[p], qB[p], sa, sb);
        }
        // shared rows dd = 8b-3 .. 8b+7; row n-dd serves (p, i = dd+p)
#pragma unroll
        for (int t = 0; t < 11; ++t) {
            const int dd = 8 * b - 3 + t;
            float4 ka, kc2;
            const bool rv = (dd <= 0) || !CHECK || (n >= dd);
            if (rv) load_row2(false, kb + (size_t)(n - dd) * HD, c, ka, kc2);
            else { ka = f4zero(); kc2 = f4zero(); }
#pragma unroll
            for (int p = 0; p < 4; ++p) {
                const int i = dd + p;
                if (i >= 8 * b && i < 8 * b + 8)
                    part[p][i - 8 * b] += d8(qA[p], qB[p], ka, kc2);
            }
        }
#pragma unroll
        for (int p = 0; p < 4; ++p) {
            const float hs = treduce8(part[p], c);
            const float bias = sm.bias[8 * b + c];
            bool valid = true;
            if (CHECK) valid = (n + p >= 8 * b + c);
            sl[p][b] = valid ? fmaf(hs, SC, bias) : -1e30f;
        }
    }

    // ---- batch 4: offsets 32..39 (d = 32,48,64,96,128,192,256,384) ----
    {
        float part[4][8];
#pragma unroll
        for (int jj = 0; jj < 8; ++jj) {
            const int i = 32 + jj;
            const int d = off_at(i);
            const float4 sa = *reinterpret_cast<const float4*>(&sm.se[i * HD + 4 * c]);
            const float4 sb = *reinterpret_cast<const float4*>(&sm.se[i * HD + 32 + 4 * c]);
#pragma unroll
            for (int p = 0; p < 4; ++p) {
                float4 ra, rb2;
                const bool v = !CHECK || (n + p >= d);
                if (v) load_row2(d >= 192, kb + (size_t)(n + p - d) * HD, c, ra, rb2);
                else { ra = f4zero(); rb2 = f4zero(); }
                part[p][jj] = d8s(qA[p], qB[p], ra, rb2, sa, sb);
            }
        }
#pragma unroll
        for (int p = 0; p < 4; ++p) {
            const float hs = treduce8(part[p], c);
            const float bias = sm.bias[32 + c];
            bool valid = true;
            if (CHECK) valid = (n + p >= sm.doff[32 + c]);
            sl[p][4] = valid ? fmaf(hs, SC, bias) : -1e30f;
        }
    }

    // ---- batch 5: offsets 40..43 (d = 512,768,1024,1536) ----
    {
        float part[4][8];
#pragma unroll
        for (int p = 0; p < 4; ++p) {
            part[p][4] = 0.f; part[p][5] = 0.f; part[p][6] = 0.f; part[p][7] = 0.f;
        }
#pragma unroll
        for (int jj = 0; jj < 4; ++jj) {
            const int i = 40 + jj;
            const int d = off_at(i);
            const float4 sa = *reinterpret_cast<const float4*>(&sm.se[i * HD + 4 * c]);
            const float4 sb = *reinterpret_cast<const float4*>(&sm.se[i * HD + 32 + 4 * c]);
#pragma unroll
            for (int p = 0; p < 4; ++p) {
                float4 ra, rb2;
                const bool v = !CHECK || (n + p >= d);
                if (v) load_row2(true, kb + (size_t)(n + p - d) * HD, c, ra, rb2);
                else { ra = f4zero(); rb2 = f4zero(); }
                part[p][jj] = d8s(qA[p], qB[p], ra, rb2, sa, sb);
            }
        }
#pragma unroll
        for (int p = 0; p < 4; ++p) {
            const float hs = treduce8(part[p], c);
            const float bias = sm.bias[40 + (c & 3)];
            bool valid = (c < 4);
            if (CHECK) valid = valid && (n + p >= sm.doff[40 + (c & 3)]);
            sl[p][5] = valid ? fmaf(hs, SC, bias) : -1e30f;
        }
    }

    // ---- softmax per position (distributed, deferred normalization) ----
    float inv[4];
    float ee[4][6];
#pragma unroll
    for (int p = 0; p < 4; ++p) {
        float m = sl[p][0];
#pragma unroll
        for (int j = 1; j < 6; ++j) m = fmaxf(m, sl[p][j]);
        m = grp_max(m);
        float sum = 0.f;
#pragma unroll
        for (int j = 0; j < 6; ++j) {
            const float e = __expf(sl[p][j] - m);
            ee[p][j] = e;
            sum += e;
        }
        sum = grp_sum(sum);
        inv[p] = __fdividef(1.f, sum);
    }

    // ---- output phase ----
    float4 oA[4], oB[4];
#pragma unroll
    for (int p = 0; p < 4; ++p) { oA[p] = f4zero(); oB[p] = f4zero(); }

    // weight for (i,p): broadcast e from owner lane, fold inv + cos/sin.
    auto wgt = [&](int i, int p) -> float2 {
        const float e = __shfl_sync(FULL, ee[p][i >> 3], i & 7, 8);
        const float pw = e * inv[p];
        const float2 cs = sm.cs[i];
        return make_float2(pw * cs.x, pw * cs.y);
    };
    auto racc = [&](int p, float2 w, const float4& va, const float4& vb2) {
        oA[p].x = fmaf(w.x, va.x, oA[p].x);  oA[p].x = fmaf(-w.y, va.y, oA[p].x);
        oA[p].y = fmaf(w.y, va.x, oA[p].y);  oA[p].y = fmaf( w.x, va.y, oA[p].y);
        oA[p].z = fmaf(w.x, va.z, oA[p].z);  oA[p].z = fmaf(-w.y, va.w, oA[p].z);
        oA[p].w = fmaf(w.y, va.z, oA[p].w);  oA[p].w = fmaf( w.x, va.w, oA[p].w);
        oB[p].x = fmaf(w.x, vb2.x, oB[p].x); oB[p].x = fmaf(-w.y, vb2.y, oB[p].x);
        oB[p].y = fmaf(w.y, vb2.x, oB[p].y); oB[p].y = fmaf( w.x, vb2.y, oB[p].y);
        oB[p].z = fmaf(w.x, vb2.z, oB[p].z); oB[p].z = fmaf(-w.y, vb2.w, oB[p].z);
        oB[p].w = fmaf(w.y, vb2.z, oB[p].w); oB[p].w = fmaf( w.x, vb2.w, oB[p].w);
    };

    // dense v rows dd = -3..32 in one pass (36 rows, 4-way shared)
#pragma unroll
    for (int t = 0; t < 36; ++t) {
        const int dd = t - 3;
        float4 va, vb2;
        const bool rv = (dd <= 0) || !CHECK || (n >= dd);
        if (rv) load_row2(false, vb + (size_t)(n - dd) * HD, c, va, vb2);
        else { va = f4zero(); vb2 = f4zero(); }
#pragma unroll
        for (int p = 0; p < 4; ++p) {
            const int i = dd + p;
            if (i >= 0 && i <= 32) {
                const float2 w = wgt(i, p);
                racc(p, w, va, vb2);
            }
        }
    }
    // sparse v rows (weights are 0 for invalid scores; rows zeroed anyway)
#pragma unroll
    for (int i = 33; i < 44; ++i) {
        const int d = off_at(i);
#pragma unroll
        for (int p = 0; p < 4; ++p) {
            float4 va, vb2;
            const bool v = !CHECK || (n + p >= d);
            if (v) load_row2(d >= 192, vb + (size_t)(n + p - d) * HD, c, va, vb2);
            else { va = f4zero(); vb2 = f4zero(); }
            const float2 w = wgt(i, p);
            racc(p, w, va, vb2);
        }
    }

    float* orow = ob + (size_t)n * HD;
#pragma unroll
    for (int p = 0; p < 4; ++p) {
        *reinterpret_cast<float4*>(orow + p * HD + 4 * c)      = oA[p];
        *reinterpret_cast<float4*>(orow + p * HD + 32 + 4 * c) = oB[p];
    }
}

__global__ void __launch_bounds__(NTHREADS, 1)
dsqg_kernel(const float* __restrict__ q, const float* __restrict__ k,
            const float* __restrict__ v, const float* __restrict__ pos_bias,
            const float* __restrict__ se, const float* __restrict__ phase,
            float* __restrict__ out)
{
    __shared__ Smem sm;
    const int bh  = blockIdx.y;
    const int h   = bh & (H - 1);
    const int tid = threadIdx.x;

    for (int idx = tid; idx < NOFF * HD; idx += NTHREADS) sm.se[idx] = se[idx];
    if (tid < NOFF) {
        sm.bias[tid] = pos_bias[tid * H + h];
        sm.doff[tid] = off_at(tid);
        float ss, cc;
        sincosf(phase[tid * H + h], &ss, &cc);
        sm.cs[tid] = make_float2(cc, ss);
    }
    __syncthreads();

    const size_t base = (size_t)bh * NPOS * HD;
    const float* qbp = q + base;
    const float* kbp = k + base;
    const float* vbp = v + base;
    float*       obp = out + base;

    const int warp = tid >> 5;
    const int lane = tid & 31;
    const int g    = lane >> 3;   // group in warp
    const int c    = lane & 7;    // dim chunk within group
    const int n0   = blockIdx.x * POS_PER_CTA;
    const int n    = n0 + (warp * 4 + g) * 4;

    if (n0 >= MAX_OFF) run_quad<false>(n, c, qbp, kbp, vbp, obp, sm);
    else               run_quad<true >(n, c, qbp, kbp, vbp, obp, sm);
}

} // namespace

extern "C" void kernel_launch(void* const* d_in, const int* in_sizes, int n_in,
                              void* d_out, int out_size)
{
    const float* q  = (const float*)d_in[0];
    const float* k  = (const float*)d_in[1];
    const float* v  = (const float*)d_in[2];
    const float* pb = (const float*)d_in[3];
    const float* se = (const float*)d_in[4];
    const float* ph = (const float*)d_in[5];
    float* out = (float*)d_out;

    const int B = in_sizes[0] / (H * NPOS * HD);   // expect 2
    dim3 grid(NPOS / POS_PER_CTA, B * H);
    dsqg_kernel<<<grid, NTHREADS>>>(q, k, v, pb, se, ph, out);
}